// round 1
// baseline (speedup 1.0000x reference)
#include <cuda_runtime.h>

// XdGate on site INDEX=3 of an L=8 qutrit (D=3) state vector, N = 3^8 = 6561.
//
// U = I ⊗ I ⊗ I ⊗ M ⊗ I ⊗ I ⊗ I ⊗ I, where M|i> = |(3 - i) mod 3>.
// U is a permutation: out[idx] = x[idx with site-3 trit t replaced by (3 - t) % 3].
// Site 3 (0-indexed from the most-significant trit) has stride 3^(7-3) = 81.
//
// Pure gather, 6561 floats. Launch-latency bound; single trivial kernel.

static constexpr int N_STATE = 6561;   // 3^8
static constexpr int STRIDE  = 81;     // 3^4

__global__ void xd_gate_kernel(const float* __restrict__ x,
                               float* __restrict__ out) {
    int idx = blockIdx.x * blockDim.x + threadIdx.x;
    if (idx >= N_STATE) return;

    // trit at site 3
    int t = (idx / STRIDE) % 3;
    // target source trit: (3 - t) % 3  ->  t=0 -> 0, t=1 -> 2, t=2 -> 1
    int tsrc = (3 - t) % 3;
    int src = idx + (tsrc - t) * STRIDE;

    out[idx] = x[src];
}

extern "C" void kernel_launch(void* const* d_in, const int* in_sizes, int n_in,
                              void* d_out, int out_size) {
    const float* x = (const float*)d_in[0];   // [6561, 1] float32
    // d_in[1] is M [3,3] — not needed; the permutation is baked in.
    float* out = (float*)d_out;

    const int threads = 256;
    const int blocks = (N_STATE + threads - 1) / threads;  // 26
    xd_gate_kernel<<<blocks, threads>>>(x, out);
}